// round 12
// baseline (speedup 1.0000x reference)
#include <cuda_runtime.h>
#include <cuda_fp16.h>
#include <mma.h>
#include <math.h>

using namespace nvcuda;

#define N_NODES 10000
#define N_EDGES 640000
#define D 128
#define K2 256           // GEMM K = 2*D  ([agg | self] @ [Wl ; Wr])
#define CAP 256          // per-node bucket capacity (max deg ~100 for this dist)
#define OVF_MAX 8192
#define TILE 16          // rows per fused block
#define NTHREADS 128

// ---------------- scratch (no allocations allowed) ----------------
__device__ int    g_cnt[N_NODES];
__device__ int    g_bucket[N_NODES * CAP];
__device__ int    g_ovf_cnt;
__device__ int    g_ovf[OVF_MAX * 2];       // (src,dst) pairs that overflowed
__device__ float  g_h1[N_NODES * D];
__device__ __half g_Whi[2][K2 * D];         // [Wl;Wr] hi halves, per layer
__device__ __half g_Wlo[2][K2 * D];         // residual lo halves

// ---------------- single-pass bucket scatter ----------------
__global__ void zero_kernel(int n) {
    int i = blockIdx.x * blockDim.x + threadIdx.x;
    if (i < n) g_cnt[i] = 0;
    if (i == 0) g_ovf_cnt = 0;
}

__global__ void scatter_kernel(const int* __restrict__ ei, int E, int n) {
    int e = blockIdx.x * blockDim.x + threadIdx.x;
    if (e < E) {
        int s = ei[e];       // src row
        int d = ei[E + e];   // dst row
        if (s >= 0 && s < n && d >= 0 && d < n) {
            int p = atomicAdd(&g_cnt[d], 1);
            if (p < CAP) {
                g_bucket[d * CAP + p] = s;
            } else {
                int q = atomicAdd(&g_ovf_cnt, 1);
                if (q < OVF_MAX) { g_ovf[2 * q] = s; g_ovf[2 * q + 1] = d; }
            }
        }
    }
}

// ---------------- weight split fp32 -> (hi, lo) halves, both layers ----------------
__global__ void convert_w_kernel(const float* __restrict__ Wl0, const float* __restrict__ Wr0,
                                 const float* __restrict__ Wl1, const float* __restrict__ Wr1) {
    int i = blockIdx.x * blockDim.x + threadIdx.x;   // 0 .. 2*256*128-1
    if (i >= 2 * K2 * D) return;
    int layer = i >> 15;           // /(256*128)
    int rc    = i & 32767;
    int r     = rc >> 7;           // 0..255
    int c     = rc & 127;
    const float* W = (layer == 0) ? (r < D ? Wl0 : Wr0) : (r < D ? Wl1 : Wr1);
    float v = W[(r & (D - 1)) * D + c];
    __half hi = __float2half_rn(v);
    __half lo = __float2half_rn(v - __half2float(hi));
    g_Whi[layer][rc] = hi;
    g_Wlo[layer][rc] = lo;
}

// ---------------- fused layer: out = elu(mean_nbr(X)@Wl + X@Wr + b) ----------------
// Phase A: 4 warps, 4 nodes/warp fp32 gather + mean; split-write into Ahi/Alo smem (16 x 256).
// Phase B: split-fp16 3-pass wmma GEMM 16x128xK256; W chunks staged hi/lo in smem.
__global__ void __launch_bounds__(NTHREADS)
fused_layer_kernel(const float* __restrict__ Xin, bool use_h1_in,
                   int layer,
                   const float* __restrict__ bias, // [128]
                   float* __restrict__ Out, bool write_h1,
                   int n)
{
    const float* __restrict__ X = use_h1_in ? (const float*)g_h1 : Xin;
    float* __restrict__ out     = write_h1  ? (float*)g_h1 : Out;

    __shared__ __half Ahi[TILE * K2];   // 8 KB
    __shared__ __half Alo[TILE * K2];   // 8 KB
    __shared__ __half Whs[32 * D];      // 8 KB  W hi k-chunk
    __shared__ __half Wls[32 * D];      // 8 KB  W lo k-chunk
    __shared__ float  Cs[TILE * D];     // 8 KB

    int tid  = threadIdx.x;
    int warp = tid >> 5;             // 0..3
    int lane = tid & 31;
    int row0 = blockIdx.x * TILE;

    // ---------- Phase A: gather (4 nodes per warp), fp32 rows ----------
    #pragma unroll
    for (int t = 0; t < 4; t++) {
        int rt   = (warp << 2) + t;      // row in tile 0..15
        int node = row0 + rt;
        float4 m  = make_float4(0.f, 0.f, 0.f, 0.f);
        float4 sx = make_float4(0.f, 0.f, 0.f, 0.f);
        if (node < n) {
            int cnt = g_cnt[node];
            int e = cnt < CAP ? cnt : CAP;
            const int* __restrict__ bk = g_bucket + node * CAP;

            float ax = 0.f, ay = 0.f, az = 0.f, aw = 0.f;
            int i = 0;
            for (; i + 8 <= e; i += 8) {
                int j0 = bk[i + 0]; int j1 = bk[i + 1];
                int j2 = bk[i + 2]; int j3 = bk[i + 3];
                int j4 = bk[i + 4]; int j5 = bk[i + 5];
                int j6 = bk[i + 6]; int j7 = bk[i + 7];
                float4 v0 = *(const float4*)(X + (long long)j0 * D + lane * 4);
                float4 v1 = *(const float4*)(X + (long long)j1 * D + lane * 4);
                float4 v2 = *(const float4*)(X + (long long)j2 * D + lane * 4);
                float4 v3 = *(const float4*)(X + (long long)j3 * D + lane * 4);
                float4 v4 = *(const float4*)(X + (long long)j4 * D + lane * 4);
                float4 v5 = *(const float4*)(X + (long long)j5 * D + lane * 4);
                float4 v6 = *(const float4*)(X + (long long)j6 * D + lane * 4);
                float4 v7 = *(const float4*)(X + (long long)j7 * D + lane * 4);
                ax += (v0.x + v1.x) + (v2.x + v3.x) + ((v4.x + v5.x) + (v6.x + v7.x));
                ay += (v0.y + v1.y) + (v2.y + v3.y) + ((v4.y + v5.y) + (v6.y + v7.y));
                az += (v0.z + v1.z) + (v2.z + v3.z) + ((v4.z + v5.z) + (v6.z + v7.z));
                aw += (v0.w + v1.w) + (v2.w + v3.w) + ((v4.w + v5.w) + (v6.w + v7.w));
            }
            for (; i < e; i++) {
                int j = bk[i];
                float4 v = *(const float4*)(X + (long long)j * D + lane * 4);
                ax += v.x; ay += v.y; az += v.z; aw += v.w;
            }
            // overflow edges (expected none)
            int novf = g_ovf_cnt;
            if (novf > 0) {
                if (novf > OVF_MAX) novf = OVF_MAX;
                for (int q = 0; q < novf; q++) {
                    if (g_ovf[2 * q + 1] == node) {
                        int j = g_ovf[2 * q];
                        float4 v = *(const float4*)(X + (long long)j * D + lane * 4);
                        ax += v.x; ay += v.y; az += v.z; aw += v.w;
                    }
                }
            }
            float inv = 1.0f / (float)(cnt > 0 ? cnt : 1);
            m.x = ax * inv; m.y = ay * inv; m.z = az * inv; m.w = aw * inv;
            sx = *(const float4*)(X + (long long)node * D + lane * 4);
        }
        // split-write: agg -> A cols [0,128), self -> A cols [128,256)
        float mv[4] = {m.x, m.y, m.z, m.w};
        float sv[4] = {sx.x, sx.y, sx.z, sx.w};
        #pragma unroll
        for (int c = 0; c < 4; c++) {
            __half hi = __float2half_rn(mv[c]);
            Ahi[rt * K2 + lane * 4 + c] = hi;
            Alo[rt * K2 + lane * 4 + c] = __float2half_rn(mv[c] - __half2float(hi));
            __half shi = __float2half_rn(sv[c]);
            Ahi[rt * K2 + D + lane * 4 + c] = shi;
            Alo[rt * K2 + D + lane * 4 + c] = __float2half_rn(sv[c] - __half2float(shi));
        }
    }
    __syncthreads();

    // ---------- Phase B: split-fp16 wmma; warp w covers cols [32w, 32w+32) ----------
    {
        const float4* __restrict__ WhiG = (const float4*)g_Whi[layer];  // 16 float4 per row
        const float4* __restrict__ WloG = (const float4*)g_Wlo[layer];
        int n0 = warp * 32;

        wmma::fragment<wmma::accumulator, 16, 16, 16, float> acc0, acc1;
        wmma::fill_fragment(acc0, 0.0f);
        wmma::fill_fragment(acc1, 0.0f);

        #pragma unroll
        for (int k0 = 0; k0 < K2; k0 += 32) {
            // stage W chunk rows [k0, k0+32) hi+lo: 512 float4 each, 4/thread each
            #pragma unroll
            for (int l = 0; l < 4; l++) {
                int idx = tid + l * NTHREADS;   // 0..511
                int r   = idx >> 4;             // 0..31
                int c8  = idx & 15;             // float4 within 128-half row
                ((float4*)Whs)[r * 16 + c8] = WhiG[(k0 + r) * 16 + c8];
                ((float4*)Wls)[r * 16 + c8] = WloG[(k0 + r) * 16 + c8];
            }
            __syncthreads();
            #pragma unroll
            for (int ks = 0; ks < 2; ks++) {
                wmma::fragment<wmma::matrix_a, 16, 16, 16, __half, wmma::row_major> ah, al;
                wmma::load_matrix_sync(ah, Ahi + k0 + 16 * ks, K2);
                wmma::load_matrix_sync(al, Alo + k0 + 16 * ks, K2);

                wmma::fragment<wmma::matrix_b, 16, 16, 16, __half, wmma::row_major> bh, bl;
                // n-tile 0
                wmma::load_matrix_sync(bh, Whs + (16 * ks) * D + n0, D);
                wmma::load_matrix_sync(bl, Wls + (16 * ks) * D + n0, D);
                wmma::mma_sync(acc0, ah, bh, acc0);
                wmma::mma_sync(acc0, ah, bl, acc0);
                wmma::mma_sync(acc0, al, bh, acc0);
                // n-tile 1
                wmma::load_matrix_sync(bh, Whs + (16 * ks) * D + n0 + 16, D);
                wmma::load_matrix_sync(bl, Wls + (16 * ks) * D + n0 + 16, D);
                wmma::mma_sync(acc1, ah, bh, acc1);
                wmma::mma_sync(acc1, ah, bl, acc1);
                wmma::mma_sync(acc1, al, bh, acc1);
            }
            __syncthreads();
        }
        wmma::store_matrix_sync(Cs + n0, acc0, D, wmma::mem_row_major);
        wmma::store_matrix_sync(Cs + n0 + 16, acc1, D, wmma::mem_row_major);
    }
    __syncthreads();

    // ---------- epilogue: bias + ELU + store ----------
    int tx = tid & 31;   // col group: cols tx*4 .. tx*4+3
    int ty = tid >> 5;   // 0..3: rows ty + 4*r
    float4 bv = *(const float4*)(bias + tx * 4);
    #pragma unroll
    for (int r = 0; r < 4; r++) {
        int rt = ty + r * 4;
        int gr = row0 + rt;
        if (gr < n) {
            float4 o = *(const float4*)(Cs + rt * D + tx * 4);
            o.x += bv.x; o.y += bv.y; o.z += bv.z; o.w += bv.w;
            o.x = o.x > 0.f ? o.x : (__expf(o.x) - 1.0f);
            o.y = o.y > 0.f ? o.y : (__expf(o.y) - 1.0f);
            o.z = o.z > 0.f ? o.z : (__expf(o.z) - 1.0f);
            o.w = o.w > 0.f ? o.w : (__expf(o.w) - 1.0f);
            *(float4*)(out + (long long)gr * D + tx * 4) = o;
        }
    }
}

// ---------------- launch ----------------
extern "C" void kernel_launch(void* const* d_in, const int* in_sizes, int n_in,
                              void* d_out, int out_size) {
    const float* x   = (const float*)d_in[0];
    const int*   ei  = (const int*)d_in[1];      // int32 edge_index [2, E]
    const float* Wl0 = (const float*)d_in[2];
    const float* b0  = (const float*)d_in[3];
    const float* Wr0 = (const float*)d_in[4];
    const float* Wl1 = (const float*)d_in[5];
    const float* b1  = (const float*)d_in[6];
    const float* Wr1 = (const float*)d_in[7];
    float*       out = (float*)d_out;

    const int N = in_sizes[0] / D;          // 10000
    const int E = in_sizes[1] / 2;          // 640000

    // bucket build + weight split (rebuilt every launch; deterministic)
    zero_kernel<<<(N + 255) / 256, 256>>>(N);
    scatter_kernel<<<(E + 255) / 256, 256>>>(ei, E, N);
    convert_w_kernel<<<(2 * K2 * D + 255) / 256, 256>>>(Wl0, Wr0, Wl1, Wr1);

    const int blocks = (N + TILE - 1) / TILE;      // 625

    // layer 0: fused agg+tensor-gemm -> g_h1
    fused_layer_kernel<<<blocks, NTHREADS>>>(x, false, 0, b0, nullptr, true, N);
    // layer 1: fused agg+tensor-gemm -> d_out
    fused_layer_kernel<<<blocks, NTHREADS>>>(nullptr, true, 1, b1, out, false, N);
}

// round 13
// speedup vs baseline: 1.2648x; 1.2648x over previous
#include <cuda_runtime.h>
#include <cuda_fp16.h>
#include <mma.h>
#include <math.h>

using namespace nvcuda;

#define N_NODES 10000
#define N_EDGES 640000
#define D 128
#define K2 256           // GEMM K = 2*D  ([agg | self] @ [Wl ; Wr])
#define CAP 256          // per-node bucket capacity (max deg ~100 for this dist)
#define OVF_MAX 8192
#define TILE 64          // rows per fused block
#define NTHREADS 256
#define A_LD 264         // halves; 528B row stride (conflict-free ldmatrix)
#define W_LD 136         // halves; 272B
#define C_LD 132         // floats; 528B

#define A_BYTES (2 * TILE * A_LD * 2)                  // Ahi+Alo = 67584
#define W_BYTES (2 * 32 * W_LD * 2)                    // Whs+Wls = 17408
#define C_BYTES (TILE * C_LD * 4)                      // 33792
#define SMEM_BYTES (A_BYTES + (C_BYTES > W_BYTES ? C_BYTES : W_BYTES))  // 101376

// ---------------- scratch (no allocations allowed) ----------------
__device__ int    g_cnt[N_NODES];
__device__ int    g_bucket[N_NODES * CAP];
__device__ int    g_ovf_cnt;
__device__ int    g_ovf[OVF_MAX * 2];       // (src,dst) pairs that overflowed
__device__ float  g_h1[N_NODES * D];
__device__ __half g_Whi[2][K2 * D];         // [Wl;Wr] hi halves, per layer
__device__ __half g_Wlo[2][K2 * D];         // residual lo halves

// ---------------- prep: zero counters + split weights (one kernel) ----------------
__global__ void prep_kernel(const float* __restrict__ Wl0, const float* __restrict__ Wr0,
                            const float* __restrict__ Wl1, const float* __restrict__ Wr1,
                            int n) {
    int i = blockIdx.x * blockDim.x + threadIdx.x;
    if (i < n) g_cnt[i] = 0;
    if (i == 0) g_ovf_cnt = 0;
    if (i < 2 * K2 * D) {
        int layer = i >> 15;           // /(256*128)
        int rc    = i & 32767;
        int r     = rc >> 7;           // 0..255
        int c     = rc & 127;
        const float* W = (layer == 0) ? (r < D ? Wl0 : Wr0) : (r < D ? Wl1 : Wr1);
        float v = W[(r & (D - 1)) * D + c];
        __half hi = __float2half_rn(v);
        g_Whi[layer][rc] = hi;
        g_Wlo[layer][rc] = __float2half_rn(v - __half2float(hi));
    }
}

// ---------------- single-pass bucket scatter ----------------
__global__ void scatter_kernel(const int* __restrict__ ei, int E, int n) {
    int e = blockIdx.x * blockDim.x + threadIdx.x;
    if (e < E) {
        int s = ei[e];       // src row
        int d = ei[E + e];   // dst row
        if (s >= 0 && s < n && d >= 0 && d < n) {
            int p = atomicAdd(&g_cnt[d], 1);
            if (p < CAP) {
                g_bucket[d * CAP + p] = s;
            } else {
                int q = atomicAdd(&g_ovf_cnt, 1);
                if (q < OVF_MAX) { g_ovf[2 * q] = s; g_ovf[2 * q + 1] = d; }
            }
        }
    }
}

// ---------------- fused layer: out = elu(mean_nbr(X)@Wl + X@Wr + b) ----------------
// Phase A: 8 warps, 8 nodes/warp fp32 gather + mean; split-write into Ahi/Alo smem (64 x 256, padded).
// Phase B: split-fp16 3-pass wmma GEMM 64x128xK256; W hi/lo chunks staged in padded smem.
__global__ void __launch_bounds__(NTHREADS)
fused_layer_kernel(const float* __restrict__ Xin, bool use_h1_in,
                   int layer,
                   const float* __restrict__ bias, // [128]
                   float* __restrict__ Out, bool write_h1,
                   int n)
{
    const float* __restrict__ X = use_h1_in ? (const float*)g_h1 : Xin;
    float* __restrict__ out     = write_h1  ? (float*)g_h1 : Out;

    extern __shared__ char smem[];
    __half* Ahi = (__half*)smem;
    __half* Alo = Ahi + TILE * A_LD;
    __half* Whs = (__half*)(smem + A_BYTES);
    __half* Wls = Whs + 32 * W_LD;
    float*  Cs  = (float*)(smem + A_BYTES);   // reuses W region after GEMM

    int tid  = threadIdx.x;
    int warp = tid >> 5;             // 0..7
    int lane = tid & 31;
    int row0 = blockIdx.x * TILE;

    // ---------- Phase A: gather (8 nodes per warp), fp32 rows ----------
    #pragma unroll 1
    for (int t = 0; t < 8; t++) {
        int rt   = (warp << 3) + t;      // row in tile 0..63
        int node = row0 + rt;
        float4 m  = make_float4(0.f, 0.f, 0.f, 0.f);
        float4 sx = make_float4(0.f, 0.f, 0.f, 0.f);
        if (node < n) {
            int cnt = g_cnt[node];
            int e = cnt < CAP ? cnt : CAP;
            const int* __restrict__ bk = g_bucket + node * CAP;

            float ax = 0.f, ay = 0.f, az = 0.f, aw = 0.f;
            int i = 0;
            for (; i + 8 <= e; i += 8) {
                int j0 = bk[i + 0]; int j1 = bk[i + 1];
                int j2 = bk[i + 2]; int j3 = bk[i + 3];
                int j4 = bk[i + 4]; int j5 = bk[i + 5];
                int j6 = bk[i + 6]; int j7 = bk[i + 7];
                float4 v0 = *(const float4*)(X + (long long)j0 * D + lane * 4);
                float4 v1 = *(const float4*)(X + (long long)j1 * D + lane * 4);
                float4 v2 = *(const float4*)(X + (long long)j2 * D + lane * 4);
                float4 v3 = *(const float4*)(X + (long long)j3 * D + lane * 4);
                float4 v4 = *(const float4*)(X + (long long)j4 * D + lane * 4);
                float4 v5 = *(const float4*)(X + (long long)j5 * D + lane * 4);
                float4 v6 = *(const float4*)(X + (long long)j6 * D + lane * 4);
                float4 v7 = *(const float4*)(X + (long long)j7 * D + lane * 4);
                ax += (v0.x + v1.x) + (v2.x + v3.x) + ((v4.x + v5.x) + (v6.x + v7.x));
                ay += (v0.y + v1.y) + (v2.y + v3.y) + ((v4.y + v5.y) + (v6.y + v7.y));
                az += (v0.z + v1.z) + (v2.z + v3.z) + ((v4.z + v5.z) + (v6.z + v7.z));
                aw += (v0.w + v1.w) + (v2.w + v3.w) + ((v4.w + v5.w) + (v6.w + v7.w));
            }
            for (; i < e; i++) {
                int j = bk[i];
                float4 v = *(const float4*)(X + (long long)j * D + lane * 4);
                ax += v.x; ay += v.y; az += v.z; aw += v.w;
            }
            // overflow edges (expected none)
            int novf = g_ovf_cnt;
            if (novf > 0) {
                if (novf > OVF_MAX) novf = OVF_MAX;
                for (int q = 0; q < novf; q++) {
                    if (g_ovf[2 * q + 1] == node) {
                        int j = g_ovf[2 * q];
                        float4 v = *(const float4*)(X + (long long)j * D + lane * 4);
                        ax += v.x; ay += v.y; az += v.z; aw += v.w;
                    }
                }
            }
            float inv = 1.0f / (float)(cnt > 0 ? cnt : 1);
            m.x = ax * inv; m.y = ay * inv; m.z = az * inv; m.w = aw * inv;
            sx = *(const float4*)(X + (long long)node * D + lane * 4);
        }
        // split-write: agg -> A cols [0,128), self -> A cols [128,256)
        float mv[4] = {m.x, m.y, m.z, m.w};
        float sv[4] = {sx.x, sx.y, sx.z, sx.w};
        #pragma unroll
        for (int c = 0; c < 4; c++) {
            __half hi = __float2half_rn(mv[c]);
            Ahi[rt * A_LD + lane * 4 + c] = hi;
            Alo[rt * A_LD + lane * 4 + c] = __float2half_rn(mv[c] - __half2float(hi));
            __half shi = __float2half_rn(sv[c]);
            Ahi[rt * A_LD + D + lane * 4 + c] = shi;
            Alo[rt * A_LD + D + lane * 4 + c] = __float2half_rn(sv[c] - __half2float(shi));
        }
    }
    __syncthreads();

    // ---------- Phase B: split-fp16 wmma; warp = 16-row band x 64-col half ----------
    {
        const float4* __restrict__ WhiG = (const float4*)g_Whi[layer];  // 16 float4/row
        const float4* __restrict__ WloG = (const float4*)g_Wlo[layer];
        int wr = (warp >> 1) * 16;     // row band
        int wc = (warp & 1) * 64;      // col offset

        wmma::fragment<wmma::accumulator, 16, 16, 16, float> acc[4];
        #pragma unroll
        for (int t = 0; t < 4; t++) wmma::fill_fragment(acc[t], 0.0f);
        wmma::fragment<wmma::matrix_a, 16, 16, 16, __half, wmma::row_major> ah, al;
        wmma::fragment<wmma::matrix_b, 16, 16, 16, __half, wmma::row_major> bh, bl;

        #pragma unroll
        for (int k0 = 0; k0 < K2; k0 += 32) {
            // stage W rows [k0, k0+32) hi+lo: 512 float4 each, 2 per thread each
            #pragma unroll
            for (int l = 0; l < 2; l++) {
                int idx = tid + l * NTHREADS;   // 0..511
                int r   = idx >> 4;             // 0..31
                int c8  = idx & 15;             // float4 (8 halves) within row
                *(float4*)(Whs + r * W_LD + c8 * 8) = WhiG[(k0 + r) * 16 + c8];
                *(float4*)(Wls + r * W_LD + c8 * 8) = WloG[(k0 + r) * 16 + c8];
            }
            __syncthreads();
            #pragma unroll
            for (int ks = 0; ks < 2; ks++) {
                wmma::load_matrix_sync(ah, Ahi + wr * A_LD + k0 + 16 * ks, A_LD);
                wmma::load_matrix_sync(al, Alo + wr * A_LD + k0 + 16 * ks, A_LD);
                #pragma unroll
                for (int t = 0; t < 4; t++) {
                    wmma::load_matrix_sync(bh, Whs + (16 * ks) * W_LD + wc + 16 * t, W_LD);
                    wmma::load_matrix_sync(bl, Wls + (16 * ks) * W_LD + wc + 16 * t, W_LD);
                    wmma::mma_sync(acc[t], ah, bh, acc[t]);
                    wmma::mma_sync(acc[t], ah, bl, acc[t]);
                    wmma::mma_sync(acc[t], al, bh, acc[t]);
                }
            }
            __syncthreads();
        }
        // all warps past last W read (trailing sync) -> safe to alias W region with Cs
        #pragma unroll
        for (int t = 0; t < 4; t++)
            wmma::store_matrix_sync(Cs + wr * C_LD + wc + 16 * t, acc[t], C_LD,
                                    wmma::mem_row_major);
    }
    __syncthreads();

    // ---------- epilogue: bias + ELU + store ----------
    int tx = tid & 31;   // col group: cols tx*4 .. tx*4+3
    int ty = tid >> 5;   // 0..7: rows ty + 8*r
    float4 bv = *(const float4*)(bias + tx * 4);
    #pragma unroll
    for (int r = 0; r < 8; r++) {
        int rt = ty + r * 8;
        int gr = row0 + rt;
        if (gr < n) {
            float4 o;
            o.x = Cs[rt * C_LD + tx * 4 + 0] + bv.x;
            o.y = Cs[rt * C_LD + tx * 4 + 1] + bv.y;
            o.z = Cs[rt * C_LD + tx * 4 + 2] + bv.z;
            o.w = Cs[rt * C_LD + tx * 4 + 3] + bv.w;
            o.x = o.x > 0.f ? o.x : (__expf(o.x) - 1.0f);
            o.y = o.y > 0.f ? o.y : (__expf(o.y) - 1.0f);
            o.z = o.z > 0.f ? o.z : (__expf(o.z) - 1.0f);
            o.w = o.w > 0.f ? o.w : (__expf(o.w) - 1.0f);
            *(float4*)(out + (long long)gr * D + tx * 4) = o;
        }
    }
}

// ---------------- launch ----------------
extern "C" void kernel_launch(void* const* d_in, const int* in_sizes, int n_in,
                              void* d_out, int out_size) {
    const float* x   = (const float*)d_in[0];
    const int*   ei  = (const int*)d_in[1];      // int32 edge_index [2, E]
    const float* Wl0 = (const float*)d_in[2];
    const float* b0  = (const float*)d_in[3];
    const float* Wr0 = (const float*)d_in[4];
    const float* Wl1 = (const float*)d_in[5];
    const float* b1  = (const float*)d_in[6];
    const float* Wr1 = (const float*)d_in[7];
    float*       out = (float*)d_out;

    const int N = in_sizes[0] / D;          // 10000
    const int E = in_sizes[1] / 2;          // 640000

    cudaFuncSetAttribute(fused_layer_kernel,
                         cudaFuncAttributeMaxDynamicSharedMemorySize, SMEM_BYTES);

    // prep (zero cnt + split W) then bucket scatter
    prep_kernel<<<(2 * K2 * D + 255) / 256, 256>>>(Wl0, Wr0, Wl1, Wr1, N);
    scatter_kernel<<<(E + 255) / 256, 256>>>(ei, E, N);

    const int blocks = (N + TILE - 1) / TILE;      // 157

    // layer 0: fused agg+tensor-gemm -> g_h1
    fused_layer_kernel<<<blocks, NTHREADS, SMEM_BYTES>>>(x, false, 0, b0, nullptr, true, N);
    // layer 1: fused agg+tensor-gemm -> d_out
    fused_layer_kernel<<<blocks, NTHREADS, SMEM_BYTES>>>(nullptr, true, 1, b1, out, false, N);
}

// round 14
// speedup vs baseline: 1.3125x; 1.0377x over previous
#include <cuda_runtime.h>
#include <cuda_bf16.h>
#include <math.h>

#define N_NODES 10000
#define N_EDGES 640000
#define D 128
#define NSUB 4           // sub-counters per node (atomic contention / 4)
#define SUBCAP 64        // slots per sub-bucket (deg/4 ~ 16, max ~40)
#define CAP (NSUB * SUBCAP)
#define OVF_MAX 8192
#define TILE 16          // rows per fused block
#define NTHREADS 128

// ---------------- scratch (no allocations allowed) ----------------
__device__ int   g_cnt4[N_NODES * NSUB];
__device__ int   g_bucket[N_NODES * CAP];
__device__ int   g_ovf_cnt;
__device__ int   g_ovf[OVF_MAX * 2];     // (src,dst) pairs that overflowed
__device__ float g_h1[N_NODES * D];

// ---------------- zero + single-pass sub-bucket scatter ----------------
__global__ void zero_kernel(int n4) {
    int i = blockIdx.x * blockDim.x + threadIdx.x;
    if (i < n4) g_cnt4[i] = 0;
    if (i == 0) g_ovf_cnt = 0;
}

__global__ void scatter_kernel(const int* __restrict__ ei, int E, int n) {
    int e = blockIdx.x * blockDim.x + threadIdx.x;
    if (e < E) {
        int s = ei[e];       // src row
        int d = ei[E + e];   // dst row
        if (s >= 0 && s < n && d >= 0 && d < n) {
            int sub = e & (NSUB - 1);
            int p = atomicAdd(&g_cnt4[d * NSUB + sub], 1);
            if (p < SUBCAP) {
                g_bucket[d * CAP + sub * SUBCAP + p] = s;
            } else {
                int q = atomicAdd(&g_ovf_cnt, 1);
                if (q < OVF_MAX) { g_ovf[2 * q] = s; g_ovf[2 * q + 1] = d; }
            }
        }
    }
}

// ---------------- fused layer: out = elu(mean_nbr(X)@Wl + X@Wr + b) ----------------
// Phase A: 4 warps, 4 nodes per warp: gather+mean into smem As, stage X into Xs.
// Phase B: 16x128 GEMM over K=256 ([As | Xs] @ [Wl ; Wr]) + bias + ELU.
__global__ void __launch_bounds__(NTHREADS)
fused_layer_kernel(const float* __restrict__ Xin, bool use_h1_in,
                   const float* __restrict__ Wl,   // [128,128]
                   const float* __restrict__ Wr,   // [128,128]
                   const float* __restrict__ bias, // [128]
                   float* __restrict__ Out, bool write_h1,
                   int n)
{
    const float* __restrict__ X = use_h1_in ? (const float*)g_h1 : Xin;
    float* __restrict__ out     = write_h1  ? (float*)g_h1 : Out;

    __shared__ float As[TILE * D];   // 8 KB  aggregated means
    __shared__ float Xs[TILE * D];   // 8 KB  self features
    __shared__ float Bs[32 * D];     // 16 KB W k-chunk

    int tid  = threadIdx.x;
    int warp = tid >> 5;             // 0..3
    int lane = tid & 31;
    int row0 = blockIdx.x * TILE;

    // ---------- Phase A: gather (4 nodes per warp) ----------
    #pragma unroll
    for (int t = 0; t < 4; t++) {
        int rt   = (warp << 2) + t;      // row in tile 0..15
        int node = row0 + rt;
        if (node < n) {
            int4 c4 = *(const int4*)(g_cnt4 + node * NSUB);
            int cnt = c4.x + c4.y + c4.z + c4.w;   // true degree (incl. overflowed)
            int ecnt[NSUB] = {
                c4.x < SUBCAP ? c4.x : SUBCAP,
                c4.y < SUBCAP ? c4.y : SUBCAP,
                c4.z < SUBCAP ? c4.z : SUBCAP,
                c4.w < SUBCAP ? c4.w : SUBCAP };

            float ax = 0.f, ay = 0.f, az = 0.f, aw = 0.f;
            #pragma unroll
            for (int sub = 0; sub < NSUB; sub++) {
                const int* __restrict__ bk = g_bucket + node * CAP + sub * SUBCAP;
                int e = ecnt[sub];
                int i = 0;
                for (; i + 8 <= e; i += 8) {
                    int j0 = bk[i + 0]; int j1 = bk[i + 1];
                    int j2 = bk[i + 2]; int j3 = bk[i + 3];
                    int j4 = bk[i + 4]; int j5 = bk[i + 5];
                    int j6 = bk[i + 6]; int j7 = bk[i + 7];
                    float4 v0 = *(const float4*)(X + (long long)j0 * D + lane * 4);
                    float4 v1 = *(const float4*)(X + (long long)j1 * D + lane * 4);
                    float4 v2 = *(const float4*)(X + (long long)j2 * D + lane * 4);
                    float4 v3 = *(const float4*)(X + (long long)j3 * D + lane * 4);
                    float4 v4 = *(const float4*)(X + (long long)j4 * D + lane * 4);
                    float4 v5 = *(const float4*)(X + (long long)j5 * D + lane * 4);
                    float4 v6 = *(const float4*)(X + (long long)j6 * D + lane * 4);
                    float4 v7 = *(const float4*)(X + (long long)j7 * D + lane * 4);
                    ax += (v0.x + v1.x) + (v2.x + v3.x) + ((v4.x + v5.x) + (v6.x + v7.x));
                    ay += (v0.y + v1.y) + (v2.y + v3.y) + ((v4.y + v5.y) + (v6.y + v7.y));
                    az += (v0.z + v1.z) + (v2.z + v3.z) + ((v4.z + v5.z) + (v6.z + v7.z));
                    aw += (v0.w + v1.w) + (v2.w + v3.w) + ((v4.w + v5.w) + (v6.w + v7.w));
                }
                for (; i < e; i++) {
                    int j = bk[i];
                    float4 v = *(const float4*)(X + (long long)j * D + lane * 4);
                    ax += v.x; ay += v.y; az += v.z; aw += v.w;
                }
            }
            // overflow edges (expected none)
            int novf = g_ovf_cnt;
            if (novf > 0) {
                if (novf > OVF_MAX) novf = OVF_MAX;
                for (int q = 0; q < novf; q++) {
                    if (g_ovf[2 * q + 1] == node) {
                        int j = g_ovf[2 * q];
                        float4 v = *(const float4*)(X + (long long)j * D + lane * 4);
                        ax += v.x; ay += v.y; az += v.z; aw += v.w;
                    }
                }
            }
            float inv = 1.0f / (float)(cnt > 0 ? cnt : 1);
            float4 m; m.x = ax * inv; m.y = ay * inv; m.z = az * inv; m.w = aw * inv;
            *(float4*)(As + rt * D + lane * 4) = m;
            *(float4*)(Xs + rt * D + lane * 4) =
                *(const float4*)(X + (long long)node * D + lane * 4);
        } else {
            float4 z = make_float4(0.f, 0.f, 0.f, 0.f);
            *(float4*)(As + rt * D + lane * 4) = z;
            *(float4*)(Xs + rt * D + lane * 4) = z;
        }
    }
    __syncthreads();

    // ---------- Phase B: GEMM 16x128, K = 2*128 ----------
    int tx = tid & 31;   // col group: cols tx*4 .. tx*4+3
    int ty = tid >> 5;   // 0..3: rows ty + 4*r, r in 0..3

    float acc[4][4];
    #pragma unroll
    for (int r = 0; r < 4; r++)
        #pragma unroll
        for (int c = 0; c < 4; c++) acc[r][c] = 0.f;

    #pragma unroll
    for (int phase = 0; phase < 2; phase++) {
        const float* __restrict__ Ap = phase ? Xs : As;   // smem
        const float* __restrict__ Wp = phase ? Wr : Wl;   // gmem (L2)
        #pragma unroll
        for (int k0 = 0; k0 < D; k0 += 32) {
            // W chunk: 32x128 floats = 1024 float4, 8 per thread
            #pragma unroll
            for (int l = 0; l < 8; l++) {
                int idx = tid + l * NTHREADS;   // 0..1023
                int r   = idx >> 5;             // k row 0..31
                int c4  = idx & 31;
                *(float4*)(Bs + r * D + c4 * 4) =
                    *(const float4*)(Wp + (long long)(k0 + r) * D + c4 * 4);
            }
            __syncthreads();
            // inner: 4 k-steps at a time; A row values as one broadcast float4
            #pragma unroll
            for (int kk = 0; kk < 32; kk += 4) {
                float4 a0 = *(const float4*)(Ap + (ty + 0) * D + k0 + kk);
                float4 a1 = *(const float4*)(Ap + (ty + 4) * D + k0 + kk);
                float4 a2 = *(const float4*)(Ap + (ty + 8) * D + k0 + kk);
                float4 a3 = *(const float4*)(Ap + (ty + 12) * D + k0 + kk);
                #pragma unroll
                for (int j = 0; j < 4; j++) {
                    float4 bv = *(const float4*)(Bs + (kk + j) * D + tx * 4);
                    float e0 = j == 0 ? a0.x : j == 1 ? a0.y : j == 2 ? a0.z : a0.w;
                    float e1 = j == 0 ? a1.x : j == 1 ? a1.y : j == 2 ? a1.z : a1.w;
                    float e2 = j == 0 ? a2.x : j == 1 ? a2.y : j == 2 ? a2.z : a2.w;
                    float e3 = j == 0 ? a3.x : j == 1 ? a3.y : j == 2 ? a3.z : a3.w;
                    acc[0][0] += e0 * bv.x; acc[0][1] += e0 * bv.y;
                    acc[0][2] += e0 * bv.z; acc[0][3] += e0 * bv.w;
                    acc[1][0] += e1 * bv.x; acc[1][1] += e1 * bv.y;
                    acc[1][2] += e1 * bv.z; acc[1][3] += e1 * bv.w;
                    acc[2][0] += e2 * bv.x; acc[2][1] += e2 * bv.y;
                    acc[2][2] += e2 * bv.z; acc[2][3] += e2 * bv.w;
                    acc[3][0] += e3 * bv.x; acc[3][1] += e3 * bv.y;
                    acc[3][2] += e3 * bv.z; acc[3][3] += e3 * bv.w;
                }
            }
            __syncthreads();
        }
    }

    // ---------- epilogue ----------
    float4 bv = *(const float4*)(bias + tx * 4);
    #pragma unroll
    for (int r = 0; r < 4; r++) {
        int gr = row0 + ty + r * 4;
        if (gr < n) {
            float4 o;
            o.x = acc[r][0] + bv.x;
            o.y = acc[r][1] + bv.y;
            o.z = acc[r][2] + bv.z;
            o.w = acc[r][3] + bv.w;
            o.x = o.x > 0.f ? o.x : (__expf(o.x) - 1.0f);
            o.y = o.y > 0.f ? o.y : (__expf(o.y) - 1.0f);
            o.z = o.z > 0.f ? o.z : (__expf(o.z) - 1.0f);
            o.w = o.w > 0.f ? o.w : (__expf(o.w) - 1.0f);
            *(float4*)(out + (long long)gr * D + tx * 4) = o;
        }
    }
}

// ---------------- launch ----------------
extern "C" void kernel_launch(void* const* d_in, const int* in_sizes, int n_in,
                              void* d_out, int out_size) {
    const float* x   = (const float*)d_in[0];
    const int*   ei  = (const int*)d_in[1];      // int32 edge_index [2, E]
    const float* Wl0 = (const float*)d_in[2];
    const float* b0  = (const float*)d_in[3];
    const float* Wr0 = (const float*)d_in[4];
    const float* Wl1 = (const float*)d_in[5];
    const float* b1  = (const float*)d_in[6];
    const float* Wr1 = (const float*)d_in[7];
    float*       out = (float*)d_out;

    const int N = in_sizes[0] / D;          // 10000
    const int E = in_sizes[1] / 2;          // 640000

    // sub-bucket build (rebuilt every launch; deterministic set per node)
    zero_kernel<<<(N * NSUB + 255) / 256, 256>>>(N * NSUB);
    scatter_kernel<<<(E + 255) / 256, 256>>>(ei, E, N);

    const int blocks = (N + TILE - 1) / TILE;      // 625

    // layer 0: fused agg+gemm -> g_h1
    fused_layer_kernel<<<blocks, NTHREADS>>>(x, false, Wl0, Wr0, b0, nullptr, true, N);
    // layer 1: fused agg+gemm -> d_out
    fused_layer_kernel<<<blocks, NTHREADS>>>(nullptr, true, Wl1, Wr1, b1, out, false, N);
}

// round 15
// speedup vs baseline: 1.7289x; 1.3172x over previous
#include <cuda_runtime.h>
#include <cuda_fp16.h>
#include <mma.h>
#include <math.h>

using namespace nvcuda;

#define N_NODES 10000
#define N_EDGES 640000
#define D 128
#define K2 256           // GEMM K = 2*D  ([agg | self] @ [Wl ; Wr])
#define CAP 256          // per-node bucket capacity (max deg ~100 for this dist)
#define OVF_MAX 8192
#define TILE 16          // rows per fused block
#define NTHREADS 128
#define A_LD 264         // halves; 528B row stride => +16B per row mod 128B (conflict-free)
#define W_LD 136         // halves; 272B row stride => +16B per row mod 128B
#define C_LD 132         // floats; 528B row stride

// ---------------- scratch (no allocations allowed) ----------------
__device__ int    g_cnt[N_NODES];
__device__ int    g_bucket[N_NODES * CAP];
__device__ int    g_ovf_cnt;
__device__ int    g_ovf[OVF_MAX * 2];       // (src,dst) pairs that overflowed
__device__ float  g_h1[N_NODES * D];
__device__ __half g_Whi[2][K2 * D];         // [Wl;Wr] hi halves, per layer
__device__ __half g_Wlo[2][K2 * D];         // residual lo halves

// ---------------- prep: zero counters + split weights (one kernel) ----------------
__global__ void prep_kernel(const float* __restrict__ Wl0, const float* __restrict__ Wr0,
                            const float* __restrict__ Wl1, const float* __restrict__ Wr1,
                            int n) {
    int i = blockIdx.x * blockDim.x + threadIdx.x;
    if (i < n) g_cnt[i] = 0;
    if (i == 0) g_ovf_cnt = 0;
    if (i < 2 * K2 * D) {
        int layer = i >> 15;           // /(256*128)
        int rc    = i & 32767;
        int r     = rc >> 7;           // 0..255
        int c     = rc & 127;
        const float* W = (layer == 0) ? (r < D ? Wl0 : Wr0) : (r < D ? Wl1 : Wr1);
        float v = W[(r & (D - 1)) * D + c];
        __half hi = __float2half_rn(v);
        g_Whi[layer][rc] = hi;
        g_Wlo[layer][rc] = __float2half_rn(v - __half2float(hi));
    }
}

// ---------------- single-pass bucket scatter (R8 form) ----------------
__global__ void scatter_kernel(const int* __restrict__ ei, int E, int n) {
    int e = blockIdx.x * blockDim.x + threadIdx.x;
    if (e < E) {
        int s = ei[e];       // src row
        int d = ei[E + e];   // dst row
        if (s >= 0 && s < n && d >= 0 && d < n) {
            int p = atomicAdd(&g_cnt[d], 1);
            if (p < CAP) {
                g_bucket[d * CAP + p] = s;
            } else {
                int q = atomicAdd(&g_ovf_cnt, 1);
                if (q < OVF_MAX) { g_ovf[2 * q] = s; g_ovf[2 * q + 1] = d; }
            }
        }
    }
}

// ---------------- fused layer: out = elu(mean_nbr(X)@Wl + X@Wr + b) ----------------
// Phase A: 4 warps, 4 nodes/warp fp32 gather + mean; split-write into padded Ahi/Alo smem.
// Phase B: split-fp16 3-pass wmma GEMM 16x128xK256; W hi/lo chunks staged in padded smem.
__global__ void __launch_bounds__(NTHREADS)
fused_layer_kernel(const float* __restrict__ Xin, bool use_h1_in,
                   int layer,
                   const float* __restrict__ bias, // [128]
                   float* __restrict__ Out, bool write_h1,
                   int n)
{
    const float* __restrict__ X = use_h1_in ? (const float*)g_h1 : Xin;
    float* __restrict__ out     = write_h1  ? (float*)g_h1 : Out;

    __shared__ __half Ahi[TILE * A_LD];                 // 8448 B
    __shared__ __half Alo[TILE * A_LD];                 // 8448 B
    __shared__ union {
        __half W[2][32 * W_LD];                         // Whs, Wls: 17408 B
        float  C[TILE * C_LD];                          // 8448 B (reused after GEMM)
    } U;

    int tid  = threadIdx.x;
    int warp = tid >> 5;             // 0..3
    int lane = tid & 31;
    int row0 = blockIdx.x * TILE;

    // ---------- Phase A: gather (4 nodes per warp), fp32 rows ----------
    #pragma unroll
    for (int t = 0; t < 4; t++) {
        int rt   = (warp << 2) + t;      // row in tile 0..15
        int node = row0 + rt;
        float4 m  = make_float4(0.f, 0.f, 0.f, 0.f);
        float4 sx = make_float4(0.f, 0.f, 0.f, 0.f);
        if (node < n) {
            int cnt = g_cnt[node];
            int e = cnt < CAP ? cnt : CAP;
            const int* __restrict__ bk = g_bucket + node * CAP;

            float ax = 0.f, ay = 0.f, az = 0.f, aw = 0.f;
            int i = 0;
            for (; i + 8 <= e; i += 8) {
                int j0 = bk[i + 0]; int j1 = bk[i + 1];
                int j2 = bk[i + 2]; int j3 = bk[i + 3];
                int j4 = bk[i + 4]; int j5 = bk[i + 5];
                int j6 = bk[i + 6]; int j7 = bk[i + 7];
                float4 v0 = *(const float4*)(X + (long long)j0 * D + lane * 4);
                float4 v1 = *(const float4*)(X + (long long)j1 * D + lane * 4);
                float4 v2 = *(const float4*)(X + (long long)j2 * D + lane * 4);
                float4 v3 = *(const float4*)(X + (long long)j3 * D + lane * 4);
                float4 v4 = *(const float4*)(X + (long long)j4 * D + lane * 4);
                float4 v5 = *(const float4*)(X + (long long)j5 * D + lane * 4);
                float4 v6 = *(const float4*)(X + (long long)j6 * D + lane * 4);
                float4 v7 = *(const float4*)(X + (long long)j7 * D + lane * 4);
                ax += (v0.x + v1.x) + (v2.x + v3.x) + ((v4.x + v5.x) + (v6.x + v7.x));
                ay += (v0.y + v1.y) + (v2.y + v3.y) + ((v4.y + v5.y) + (v6.y + v7.y));
                az += (v0.z + v1.z) + (v2.z + v3.z) + ((v4.z + v5.z) + (v6.z + v7.z));
                aw += (v0.w + v1.w) + (v2.w + v3.w) + ((v4.w + v5.w) + (v6.w + v7.w));
            }
            for (; i < e; i++) {
                int j = bk[i];
                float4 v = *(const float4*)(X + (long long)j * D + lane * 4);
                ax += v.x; ay += v.y; az += v.z; aw += v.w;
            }
            // overflow edges (expected none)
            int novf = g_ovf_cnt;
            if (novf > 0) {
                if (novf > OVF_MAX) novf = OVF_MAX;
                for (int q = 0; q < novf; q++) {
                    if (g_ovf[2 * q + 1] == node) {
                        int j = g_ovf[2 * q];
                        float4 v = *(const float4*)(X + (long long)j * D + lane * 4);
                        ax += v.x; ay += v.y; az += v.z; aw += v.w;
                    }
                }
            }
            float inv = 1.0f / (float)(cnt > 0 ? cnt : 1);
            m.x = ax * inv; m.y = ay * inv; m.z = az * inv; m.w = aw * inv;
            sx = *(const float4*)(X + (long long)node * D + lane * 4);
        }
        // split-write: agg -> A cols [0,128), self -> A cols [128,256)
        float mv[4] = {m.x, m.y, m.z, m.w};
        float sv[4] = {sx.x, sx.y, sx.z, sx.w};
        #pragma unroll
        for (int c = 0; c < 4; c++) {
            __half hi = __float2half_rn(mv[c]);
            Ahi[rt * A_LD + lane * 4 + c] = hi;
            Alo[rt * A_LD + lane * 4 + c] = __float2half_rn(mv[c] - __half2float(hi));
            __half shi = __float2half_rn(sv[c]);
            Ahi[rt * A_LD + D + lane * 4 + c] = shi;
            Alo[rt * A_LD + D + lane * 4 + c] = __float2half_rn(sv[c] - __half2float(shi));
        }
    }
    __syncthreads();

    // ---------- Phase B: split-fp16 wmma; warp w covers cols [32w, 32w+32) ----------
    {
        const float4* __restrict__ WhiG = (const float4*)g_Whi[layer];  // 16 float4/row
        const float4* __restrict__ WloG = (const float4*)g_Wlo[layer];
        __half* Whs = U.W[0];
        __half* Wls = U.W[1];
        int n0 = warp * 32;

        wmma::fragment<wmma::accumulator, 16, 16, 16, float> acc0, acc1;
        wmma::fill_fragment(acc0, 0.0f);
        wmma::fill_fragment(acc1, 0.0f);
        wmma::fragment<wmma::matrix_a, 16, 16, 16, __half, wmma::row_major> ah, al;
        wmma::fragment<wmma::matrix_b, 16, 16, 16, __half, wmma::row_major> bh, bl;

        #pragma unroll
        for (int k0 = 0; k0 < K2; k0 += 32) {
            // stage W rows [k0, k0+32) hi+lo: 512 float4 each, 4 per thread each
            #pragma unroll
            for (int l = 0; l < 4; l++) {
                int idx = tid + l * NTHREADS;   // 0..511
                int r   = idx >> 4;             // 0..31
                int c8  = idx & 15;             // float4 (8 halves) within row
                *(float4*)(Whs + r * W_LD + c8 * 8) = WhiG[(k0 + r) * 16 + c8];
                *(float4*)(Wls + r * W_LD + c8 * 8) = WloG[(k0 + r) * 16 + c8];
            }
            __syncthreads();
            #pragma unroll
            for (int ks = 0; ks < 2; ks++) {
                wmma::load_matrix_sync(ah, Ahi + k0 + 16 * ks, A_LD);
                wmma::load_matrix_sync(al, Alo + k0 + 16 * ks, A_LD);
                // n-tile 0
                wmma::load_matrix_sync(bh, Whs + (16 * ks) * W_LD + n0, W_LD);
                wmma::load_matrix_sync(bl, Wls + (16 * ks) * W_LD + n0, W_LD);
                wmma::mma_sync(acc0, ah, bh, acc0);
                wmma::mma_sync(acc0, ah, bl, acc0);
                wmma::mma_sync(acc0, al, bh, acc0);
                // n-tile 1
                wmma::load_matrix_sync(bh, Whs + (16 * ks) * W_LD + n0 + 16, W_LD);
                wmma::load_matrix_sync(bl, Wls + (16 * ks) * W_LD + n0 + 16, W_LD);
                wmma::mma_sync(acc1, ah, bh, acc1);
                wmma::mma_sync(acc1, ah, bl, acc1);
                wmma::mma_sync(acc1, al, bh, acc1);
            }
            __syncthreads();   // also guards the W->C union reuse below
        }
        wmma::store_matrix_sync(U.C + n0, acc0, C_LD, wmma::mem_row_major);
        wmma::store_matrix_sync(U.C + n0 + 16, acc1, C_LD, wmma::mem_row_major);
    }
    __syncthreads();

    // ---------- epilogue: bias + ELU + store ----------
    int tx = tid & 31;   // col group: cols tx*4 .. tx*4+3
    int ty = tid >> 5;   // 0..3: rows ty + 4*r
    float4 bv = *(const float4*)(bias + tx * 4);
    #pragma unroll
    for (int r = 0; r < 4; r++) {
        int rt = ty + r * 4;
        int gr = row0 + rt;
        if (gr < n) {
            float4 o;
            o.x = U.C[rt * C_LD + tx * 4 + 0] + bv.x;
            o.y = U.C[rt * C_LD + tx * 4 + 1] + bv.y;
            o.z = U.C[rt * C_LD + tx * 4 + 2] + bv.z;
            o.w = U.C[rt * C_LD + tx * 4 + 3] + bv.w;
            o.x = o.x > 0.f ? o.x : (__expf(o.x) - 1.0f);
            o.y = o.y > 0.f ? o.y : (__expf(o.y) - 1.0f);
            o.z = o.z > 0.f ? o.z : (__expf(o.z) - 1.0f);
            o.w = o.w > 0.f ? o.w : (__expf(o.w) - 1.0f);
            *(float4*)(out + (long long)gr * D + tx * 4) = o;
        }
    }
}

// ---------------- launch ----------------
extern "C" void kernel_launch(void* const* d_in, const int* in_sizes, int n_in,
                              void* d_out, int out_size) {
    const float* x   = (const float*)d_in[0];
    const int*   ei  = (const int*)d_in[1];      // int32 edge_index [2, E]
    const float* Wl0 = (const float*)d_in[2];
    const float* b0  = (const float*)d_in[3];
    const float* Wr0 = (const float*)d_in[4];
    const float* Wl1 = (const float*)d_in[5];
    const float* b1  = (const float*)d_in[6];
    const float* Wr1 = (const float*)d_in[7];
    float*       out = (float*)d_out;

    const int N = in_sizes[0] / D;          // 10000
    const int E = in_sizes[1] / 2;          // 640000

    // prep (zero cnt + split W) then bucket scatter
    prep_kernel<<<(2 * K2 * D + 255) / 256, 256>>>(Wl0, Wr0, Wl1, Wr1, N);
    scatter_kernel<<<(E + 255) / 256, 256>>>(ei, E, N);

    const int blocks = (N + TILE - 1) / TILE;      // 625

    // layer 0: fused agg+tensor-gemm -> g_h1
    fused_layer_kernel<<<blocks, NTHREADS>>>(x, false, 0, b0, nullptr, true, N);
    // layer 1: fused agg+tensor-gemm -> d_out
    fused_layer_kernel<<<blocks, NTHREADS>>>(nullptr, true, 1, b1, out, false, N);
}

// round 16
// speedup vs baseline: 1.7892x; 1.0349x over previous
#include <cuda_runtime.h>
#include <cuda_fp16.h>
#include <mma.h>
#include <math.h>

using namespace nvcuda;

#define N_NODES 10000
#define N_EDGES 640000
#define D 128
#define K2 256           // GEMM K = 2*D  ([agg | self] @ [Wl ; Wr])
#define CAP 256          // per-node bucket capacity (max deg ~100 for this dist)
#define OVF_MAX 8192
#define TILE 16          // rows per fused block
#define NTHREADS 128
#define A_LD 264         // halves; 528B row stride => +16B per row mod 128B (conflict-free)
#define W_LD 136         // halves; 272B row stride => +16B per row mod 128B
#define C_LD 132         // floats; 528B row stride
#define CNT_STRIDE 32    // one counter per 128B line (LTS atomic spread)

// ---------------- scratch (no allocations allowed) ----------------
__device__ int    g_cntp[N_NODES * CNT_STRIDE];   // padded counters, 1 per 128B line
__device__ int    g_bucket[N_NODES * CAP];
__device__ int    g_ovf_cnt;
__device__ int    g_ovf[OVF_MAX * 2];       // (src,dst) pairs that overflowed
__device__ float  g_h1[N_NODES * D];
__device__ __half g_Whi[2][K2 * D];         // [Wl;Wr] hi halves, per layer
__device__ __half g_Wlo[2][K2 * D];         // residual lo halves

// ---------------- prep: zero padded counters + split weights (one kernel) ----------------
__global__ void prep_kernel(const float* __restrict__ Wl0, const float* __restrict__ Wr0,
                            const float* __restrict__ Wl1, const float* __restrict__ Wr1,
                            int n) {
    int i = blockIdx.x * blockDim.x + threadIdx.x;
    if (i < n * CNT_STRIDE) g_cntp[i] = 0;
    if (i == 0) g_ovf_cnt = 0;
    if (i < 2 * K2 * D) {
        int layer = i >> 15;           // /(256*128)
        int rc    = i & 32767;
        int r     = rc >> 7;           // 0..255
        int c     = rc & 127;
        const float* W = (layer == 0) ? (r < D ? Wl0 : Wr0) : (r < D ? Wl1 : Wr1);
        float v = W[(r & (D - 1)) * D + c];
        __half hi = __float2half_rn(v);
        g_Whi[layer][rc] = hi;
        g_Wlo[layer][rc] = __float2half_rn(v - __half2float(hi));
    }
}

// ---------------- single-pass bucket scatter (padded counters) ----------------
__global__ void scatter_kernel(const int* __restrict__ ei, int E, int n) {
    int e = blockIdx.x * blockDim.x + threadIdx.x;
    if (e < E) {
        int s = ei[e];       // src row
        int d = ei[E + e];   // dst row
        if (s >= 0 && s < n && d >= 0 && d < n) {
            int p = atomicAdd(&g_cntp[d << 5], 1);
            if (p < CAP) {
                g_bucket[d * CAP + p] = s;
            } else {
                int q = atomicAdd(&g_ovf_cnt, 1);
                if (q < OVF_MAX) { g_ovf[2 * q] = s; g_ovf[2 * q + 1] = d; }
            }
        }
    }
}

// ---------------- fused layer: out = elu(mean_nbr(X)@Wl + X@Wr + b) ----------------
// Phase A: 4 warps, 4 nodes/warp fp32 gather + mean; split-write into padded Ahi/Alo smem.
// Phase B: split-fp16 3-pass wmma GEMM 16x128xK256; W hi/lo chunks staged in padded smem.
__global__ void __launch_bounds__(NTHREADS)
fused_layer_kernel(const float* __restrict__ Xin, bool use_h1_in,
                   int layer,
                   const float* __restrict__ bias, // [128]
                   float* __restrict__ Out, bool write_h1,
                   int n)
{
    const float* __restrict__ X = use_h1_in ? (const float*)g_h1 : Xin;
    float* __restrict__ out     = write_h1  ? (float*)g_h1 : Out;

    __shared__ __half Ahi[TILE * A_LD];                 // 8448 B
    __shared__ __half Alo[TILE * A_LD];                 // 8448 B
    __shared__ union {
        __half W[2][32 * W_LD];                         // Whs, Wls: 17408 B
        float  C[TILE * C_LD];                          // 8448 B (reused after GEMM)
    } U;

    int tid  = threadIdx.x;
    int warp = tid >> 5;             // 0..3
    int lane = tid & 31;
    int row0 = blockIdx.x * TILE;

    // ---------- Phase A: gather (4 nodes per warp), fp32 rows ----------
    #pragma unroll
    for (int t = 0; t < 4; t++) {
        int rt   = (warp << 2) + t;      // row in tile 0..15
        int node = row0 + rt;
        float4 m  = make_float4(0.f, 0.f, 0.f, 0.f);
        float4 sx = make_float4(0.f, 0.f, 0.f, 0.f);
        if (node < n) {
            int cnt = g_cntp[node << 5];
            int e = cnt < CAP ? cnt : CAP;
            const int* __restrict__ bk = g_bucket + node * CAP;

            float ax = 0.f, ay = 0.f, az = 0.f, aw = 0.f;
            int i = 0;
            for (; i + 8 <= e; i += 8) {
                int j0 = bk[i + 0]; int j1 = bk[i + 1];
                int j2 = bk[i + 2]; int j3 = bk[i + 3];
                int j4 = bk[i + 4]; int j5 = bk[i + 5];
                int j6 = bk[i + 6]; int j7 = bk[i + 7];
                float4 v0 = *(const float4*)(X + (long long)j0 * D + lane * 4);
                float4 v1 = *(const float4*)(X + (long long)j1 * D + lane * 4);
                float4 v2 = *(const float4*)(X + (long long)j2 * D + lane * 4);
                float4 v3 = *(const float4*)(X + (long long)j3 * D + lane * 4);
                float4 v4 = *(const float4*)(X + (long long)j4 * D + lane * 4);
                float4 v5 = *(const float4*)(X + (long long)j5 * D + lane * 4);
                float4 v6 = *(const float4*)(X + (long long)j6 * D + lane * 4);
                float4 v7 = *(const float4*)(X + (long long)j7 * D + lane * 4);
                ax += (v0.x + v1.x) + (v2.x + v3.x) + ((v4.x + v5.x) + (v6.x + v7.x));
                ay += (v0.y + v1.y) + (v2.y + v3.y) + ((v4.y + v5.y) + (v6.y + v7.y));
                az += (v0.z + v1.z) + (v2.z + v3.z) + ((v4.z + v5.z) + (v6.z + v7.z));
                aw += (v0.w + v1.w) + (v2.w + v3.w) + ((v4.w + v5.w) + (v6.w + v7.w));
            }
            for (; i < e; i++) {
                int j = bk[i];
                float4 v = *(const float4*)(X + (long long)j * D + lane * 4);
                ax += v.x; ay += v.y; az += v.z; aw += v.w;
            }
            // overflow edges (expected none)
            int novf = g_ovf_cnt;
            if (novf > 0) {
                if (novf > OVF_MAX) novf = OVF_MAX;
                for (int q = 0; q < novf; q++) {
                    if (g_ovf[2 * q + 1] == node) {
                        int j = g_ovf[2 * q];
                        float4 v = *(const float4*)(X + (long long)j * D + lane * 4);
                        ax += v.x; ay += v.y; az += v.z; aw += v.w;
                    }
                }
            }
            float inv = 1.0f / (float)(cnt > 0 ? cnt : 1);
            m.x = ax * inv; m.y = ay * inv; m.z = az * inv; m.w = aw * inv;
            sx = *(const float4*)(X + (long long)node * D + lane * 4);
        }
        // split-write: agg -> A cols [0,128), self -> A cols [128,256)
        float mv[4] = {m.x, m.y, m.z, m.w};
        float sv[4] = {sx.x, sx.y, sx.z, sx.w};
        #pragma unroll
        for (int c = 0; c < 4; c++) {
            __half hi = __float2half_rn(mv[c]);
            Ahi[rt * A_LD + lane * 4 + c] = hi;
            Alo[rt * A_LD + lane * 4 + c] = __float2half_rn(mv[c] - __half2float(hi));
            __half shi = __float2half_rn(sv[c]);
            Ahi[rt * A_LD + D + lane * 4 + c] = shi;
            Alo[rt * A_LD + D + lane * 4 + c] = __float2half_rn(sv[c] - __half2float(shi));
        }
    }
    __syncthreads();

    // ---------- Phase B: split-fp16 wmma; warp w covers cols [32w, 32w+32) ----------
    {
        const float4* __restrict__ WhiG = (const float4*)g_Whi[layer];  // 16 float4/row
        const float4* __restrict__ WloG = (const float4*)g_Wlo[layer];
        __half* Whs = U.W[0];
        __half* Wls = U.W[1];
        int n0 = warp * 32;

        wmma::fragment<wmma::accumulator, 16, 16, 16, float> acc0, acc1;
        wmma::fill_fragment(acc0, 0.0f);
        wmma::fill_fragment(acc1, 0.0f);
        wmma::fragment<wmma::matrix_a, 16, 16, 16, __half, wmma::row_major> ah, al;
        wmma::fragment<wmma::matrix_b, 16, 16, 16, __half, wmma::row_major> bh, bl;

        #pragma unroll
        for (int k0 = 0; k0 < K2; k0 += 32) {
            // stage W rows [k0, k0+32) hi+lo: 512 float4 each, 4 per thread each
            #pragma unroll
            for (int l = 0; l < 4; l++) {
                int idx = tid + l * NTHREADS;   // 0..511
                int r   = idx >> 4;             // 0..31
                int c8  = idx & 15;             // float4 (8 halves) within row
                *(float4*)(Whs + r * W_LD + c8 * 8) = WhiG[(k0 + r) * 16 + c8];
                *(float4*)(Wls + r * W_LD + c8 * 8) = WloG[(k0 + r) * 16 + c8];
            }
            __syncthreads();
            #pragma unroll
            for (int ks = 0; ks < 2; ks++) {
                wmma::load_matrix_sync(ah, Ahi + k0 + 16 * ks, A_LD);
                wmma::load_matrix_sync(al, Alo + k0 + 16 * ks, A_LD);
                // n-tile 0
                wmma::load_matrix_sync(bh, Whs + (16 * ks) * W_LD + n0, W_LD);
                wmma::load_matrix_sync(bl, Wls + (16 * ks) * W_LD + n0, W_LD);
                wmma::mma_sync(acc0, ah, bh, acc0);
                wmma::mma_sync(acc0, ah, bl, acc0);
                wmma::mma_sync(acc0, al, bh, acc0);
                // n-tile 1
                wmma::load_matrix_sync(bh, Whs + (16 * ks) * W_LD + n0 + 16, W_LD);
                wmma::load_matrix_sync(bl, Wls + (16 * ks) * W_LD + n0 + 16, W_LD);
                wmma::mma_sync(acc1, ah, bh, acc1);
                wmma::mma_sync(acc1, ah, bl, acc1);
                wmma::mma_sync(acc1, al, bh, acc1);
            }
            __syncthreads();   // also guards the W->C union reuse below
        }
        wmma::store_matrix_sync(U.C + n0, acc0, C_LD, wmma::mem_row_major);
        wmma::store_matrix_sync(U.C + n0 + 16, acc1, C_LD, wmma::mem_row_major);
    }
    __syncthreads();

    // ---------- epilogue: bias + ELU + store ----------
    int tx = tid & 31;   // col group: cols tx*4 .. tx*4+3
    int ty = tid >> 5;   // 0..3: rows ty + 4*r
    float4 bv = *(const float4*)(bias + tx * 4);
    #pragma unroll
    for (int r = 0; r < 4; r++) {
        int rt = ty + r * 4;
        int gr = row0 + rt;
        if (gr < n) {
            float4 o;
            o.x = U.C[rt * C_LD + tx * 4 + 0] + bv.x;
            o.y = U.C[rt * C_LD + tx * 4 + 1] + bv.y;
            o.z = U.C[rt * C_LD + tx * 4 + 2] + bv.z;
            o.w = U.C[rt * C_LD + tx * 4 + 3] + bv.w;
            o.x = o.x > 0.f ? o.x : (__expf(o.x) - 1.0f);
            o.y = o.y > 0.f ? o.y : (__expf(o.y) - 1.0f);
            o.z = o.z > 0.f ? o.z : (__expf(o.z) - 1.0f);
            o.w = o.w > 0.f ? o.w : (__expf(o.w) - 1.0f);
            *(float4*)(out + (long long)gr * D + tx * 4) = o;
        }
    }
}

// ---------------- launch ----------------
extern "C" void kernel_launch(void* const* d_in, const int* in_sizes, int n_in,
                              void* d_out, int out_size) {
    const float* x   = (const float*)d_in[0];
    const int*   ei  = (const int*)d_in[1];      // int32 edge_index [2, E]
    const float* Wl0 = (const float*)d_in[2];
    const float* b0  = (const float*)d_in[3];
    const float* Wr0 = (const float*)d_in[4];
    const float* Wl1 = (const float*)d_in[5];
    const float* b1  = (const float*)d_in[6];
    const float* Wr1 = (const float*)d_in[7];
    float*       out = (float*)d_out;

    const int N = in_sizes[0] / D;          // 10000
    const int E = in_sizes[1] / 2;          // 640000

    // prep (zero padded counters + split W) then bucket scatter
    const int prepThreads = N * CNT_STRIDE;        // 320000 (covers 2*K2*D too)
    prep_kernel<<<(prepThreads + 255) / 256, 256>>>(Wl0, Wr0, Wl1, Wr1, N);
    scatter_kernel<<<(E + 255) / 256, 256>>>(ei, E, N);

    const int blocks = (N + TILE - 1) / TILE;      // 625

    // layer 0: fused agg+tensor-gemm -> g_h1
    fused_layer_kernel<<<blocks, NTHREADS>>>(x, false, 0, b0, nullptr, true, N);
    // layer 1: fused agg+tensor-gemm -> d_out
    fused_layer_kernel<<<blocks, NTHREADS>>>(nullptr, true, 1, b1, out, false, N);
}

// round 17
// speedup vs baseline: 1.8532x; 1.0358x over previous
#include <cuda_runtime.h>
#include <cuda_fp16.h>
#include <mma.h>
#include <math.h>

using namespace nvcuda;

#define N_NODES 10000
#define N_EDGES 640000
#define D 128
#define K2 256           // GEMM K = 2*D  ([agg | self] @ [Wl ; Wr])
#define CAP 256          // per-node bucket capacity (max deg ~100 for this dist)
#define OVF_MAX 8192
#define TILE 16          // rows per fused block
#define NTHREADS 128
#define A_LD 264         // halves; 528B row stride => +16B per row mod 128B (conflict-free)
#define W_LD 136         // halves; 272B row stride => +16B per row mod 128B
#define C_LD 132         // floats; 528B row stride
#define CNT_STRIDE 32    // one counter per 128B line (LTS atomic spread)

// ---------------- scratch (no allocations allowed) ----------------
__device__ int     g_cntp[N_NODES * CNT_STRIDE];   // padded counters, 1 per 128B line
__device__ int     g_bucket[N_NODES * CAP];
__device__ int     g_ovf_cnt;
__device__ int     g_ovf[OVF_MAX * 2];       // (src,dst) pairs that overflowed
__device__ float   g_h1[N_NODES * D];
__device__ __half2 g_xh[N_NODES * (D / 2)];  // fp16 mirror of current-layer input
__device__ __half  g_Whi[2][K2 * D];         // [Wl;Wr] hi halves, per layer
__device__ __half  g_Wlo[2][K2 * D];         // residual lo halves

// ---------------- prep: zero counters + split weights + x->fp16 (one kernel) ----------------
__global__ void prep_kernel(const float* __restrict__ x,
                            const float* __restrict__ Wl0, const float* __restrict__ Wr0,
                            const float* __restrict__ Wl1, const float* __restrict__ Wr1,
                            int n) {
    int i = blockIdx.x * blockDim.x + threadIdx.x;
    if (i < n * CNT_STRIDE) g_cntp[i] = 0;
    if (i == 0) g_ovf_cnt = 0;
    if (i < 2 * K2 * D) {
        int layer = i >> 15;           // /(256*128)
        int rc    = i & 32767;
        int r     = rc >> 7;           // 0..255
        int c     = rc & 127;
        const float* W = (layer == 0) ? (r < D ? Wl0 : Wr0) : (r < D ? Wl1 : Wr1);
        float v = W[(r & (D - 1)) * D + c];
        __half hi = __float2half_rn(v);
        g_Whi[layer][rc] = hi;
        g_Wlo[layer][rc] = __float2half_rn(v - __half2float(hi));
    }
    // x -> fp16 mirror: i covers n*D/4 float4s (320000 for N=10000)
    if (i < n * (D / 4)) {
        float4 v = *(const float4*)(x + 4 * (long long)i);
        g_xh[2 * i + 0] = __floats2half2_rn(v.x, v.y);
        g_xh[2 * i + 1] = __floats2half2_rn(v.z, v.w);
    }
}

// ---------------- single-pass bucket scatter (padded counters) ----------------
__global__ void scatter_kernel(const int* __restrict__ ei, int E, int n) {
    int e = blockIdx.x * blockDim.x + threadIdx.x;
    if (e < E) {
        int s = ei[e];       // src row
        int d = ei[E + e];   // dst row
        if (s >= 0 && s < n && d >= 0 && d < n) {
            int p = atomicAdd(&g_cntp[d << 5], 1);
            if (p < CAP) {
                g_bucket[d * CAP + p] = s;
            } else {
                int q = atomicAdd(&g_ovf_cnt, 1);
                if (q < OVF_MAX) { g_ovf[2 * q] = s; g_ovf[2 * q + 1] = d; }
            }
        }
    }
}

// ---------------- fused layer: out = elu(mean_nbr(X)@Wl + X@Wr + b) ----------------
// Phase A: 4 warps, 4 nodes/warp gather fp16 rows (g_xh) + mean; split into Ahi/Alo smem.
// Phase B: split-fp16 3-pass wmma GEMM 16x128xK256; W hi/lo chunks staged in padded smem.
// Layer 0 (write_h1): epilogue dual-writes g_h1 (fp32) and g_xh (fp16) for layer 1.
__global__ void __launch_bounds__(NTHREADS)
fused_layer_kernel(const float* __restrict__ Xin, bool use_h1_in,
                   int layer,
                   const float* __restrict__ bias, // [128]
                   float* __restrict__ Out, bool write_h1,
                   int n)
{
    const float* __restrict__ X = use_h1_in ? (const float*)g_h1 : Xin;
    float* __restrict__ out     = write_h1  ? (float*)g_h1 : Out;

    __shared__ __half Ahi[TILE * A_LD];                 // 8448 B
    __shared__ __half Alo[TILE * A_LD];                 // 8448 B
    __shared__ union {
        __half W[2][32 * W_LD];                         // Whs, Wls: 17408 B
        float  C[TILE * C_LD];                          // 8448 B (reused after GEMM)
    } U;

    int tid  = threadIdx.x;
    int warp = tid >> 5;             // 0..3
    int lane = tid & 31;
    int row0 = blockIdx.x * TILE;

    // ---------- Phase A: gather (4 nodes per warp), fp16 rows from g_xh ----------
    #pragma unroll
    for (int t = 0; t < 4; t++) {
        int rt   = (warp << 2) + t;      // row in tile 0..15
        int node = row0 + rt;
        float4 m  = make_float4(0.f, 0.f, 0.f, 0.f);
        float4 sx = make_float4(0.f, 0.f, 0.f, 0.f);
        if (node < n) {
            int cnt = g_cntp[node << 5];
            int e = cnt < CAP ? cnt : CAP;
            const int* __restrict__ bk = g_bucket + node * CAP;

            float ax = 0.f, ay = 0.f, az = 0.f, aw = 0.f;
            int i = 0;
            for (; i + 8 <= e; i += 8) {
                #pragma unroll
                for (int u = 0; u < 8; u++) {
                    int j = bk[i + u];
                    uint2 raw = *(const uint2*)(g_xh + (long long)j * (D / 2) + lane * 2);
                    float2 f01 = __half22float2(*(__half2*)&raw.x);
                    float2 f23 = __half22float2(*(__half2*)&raw.y);
                    ax += f01.x; ay += f01.y; az += f23.x; aw += f23.y;
                }
            }
            for (; i < e; i++) {
                int j = bk[i];
                uint2 raw = *(const uint2*)(g_xh + (long long)j * (D / 2) + lane * 2);
                float2 f01 = __half22float2(*(__half2*)&raw.x);
                float2 f23 = __half22float2(*(__half2*)&raw.y);
                ax += f01.x; ay += f01.y; az += f23.x; aw += f23.y;
            }
            // overflow edges (expected none)
            int novf = g_ovf_cnt;
            if (novf > 0) {
                if (novf > OVF_MAX) novf = OVF_MAX;
                for (int q = 0; q < novf; q++) {
                    if (g_ovf[2 * q + 1] == node) {
                        int j = g_ovf[2 * q];
                        uint2 raw = *(const uint2*)(g_xh + (long long)j * (D / 2) + lane * 2);
                        float2 f01 = __half22float2(*(__half2*)&raw.x);
                        float2 f23 = __half22float2(*(__half2*)&raw.y);
                        ax += f01.x; ay += f01.y; az += f23.x; aw += f23.y;
                    }
                }
            }
            float inv = 1.0f / (float)(cnt > 0 ? cnt : 1);
            m.x = ax * inv; m.y = ay * inv; m.z = az * inv; m.w = aw * inv;
            sx = *(const float4*)(X + (long long)node * D + lane * 4);   // self: fp32
        }
        // split-write: agg -> A cols [0,128), self -> A cols [128,256)
        float mv[4] = {m.x, m.y, m.z, m.w};
        float sv[4] = {sx.x, sx.y, sx.z, sx.w};
        #pragma unroll
        for (int c = 0; c < 4; c++) {
            __half hi = __float2half_rn(mv[c]);
            Ahi[rt * A_LD + lane * 4 + c] = hi;
            Alo[rt * A_LD + lane * 4 + c] = __float2half_rn(mv[c] - __half2float(hi));
            __half shi = __float2half_rn(sv[c]);
            Ahi[rt * A_LD + D + lane * 4 + c] = shi;
            Alo[rt * A_LD + D + lane * 4 + c] = __float2half_rn(sv[c] - __half2float(shi));
        }
    }
    __syncthreads();

    // ---------- Phase B: split-fp16 wmma; warp w covers cols [32w, 32w+32) ----------
    {
        const float4* __restrict__ WhiG = (const float4*)g_Whi[layer];  // 16 float4/row
        const float4* __restrict__ WloG = (const float4*)g_Wlo[layer];
        __half* Whs = U.W[0];
        __half* Wls = U.W[1];
        int n0 = warp * 32;

        wmma::fragment<wmma::accumulator, 16, 16, 16, float> acc0, acc1;
        wmma::fill_fragment(acc0, 0.0f);
        wmma::fill_fragment(acc1, 0.0f);
        wmma::fragment<wmma::matrix_a, 16, 16, 16, __half, wmma::row_major> ah, al;
        wmma::fragment<wmma::matrix_b, 16, 16, 16, __half, wmma::row_major> bh, bl;

        #pragma unroll
        for (int k0 = 0; k0 < K2; k0 += 32) {
            // stage W rows [k0, k0+32) hi+lo: 512 float4 each, 4 per thread each
            #pragma unroll
            for (int l = 0; l < 4; l++) {
                int idx = tid + l * NTHREADS;   // 0..511
                int r   = idx >> 4;             // 0..31
                int c8  = idx & 15;             // float4 (8 halves) within row
                *(float4*)(Whs + r * W_LD + c8 * 8) = WhiG[(k0 + r) * 16 + c8];
                *(float4*)(Wls + r * W_LD + c8 * 8) = WloG[(k0 + r) * 16 + c8];
            }
            __syncthreads();
            #pragma unroll
            for (int ks = 0; ks < 2; ks++) {
                wmma::load_matrix_sync(ah, Ahi + k0 + 16 * ks, A_LD);
                wmma::load_matrix_sync(al, Alo + k0 + 16 * ks, A_LD);
                // n-tile 0
                wmma::load_matrix_sync(bh, Whs + (16 * ks) * W_LD + n0, W_LD);
                wmma::load_matrix_sync(bl, Wls + (16 * ks) * W_LD + n0, W_LD);
                wmma::mma_sync(acc0, ah, bh, acc0);
                wmma::mma_sync(acc0, ah, bl, acc0);
                wmma::mma_sync(acc0, al, bh, acc0);
                // n-tile 1
                wmma::load_matrix_sync(bh, Whs + (16 * ks) * W_LD + n0 + 16, W_LD);
                wmma::load_matrix_sync(bl, Wls + (16 * ks) * W_LD + n0 + 16, W_LD);
                wmma::mma_sync(acc1, ah, bh, acc1);
                wmma::mma_sync(acc1, ah, bl, acc1);
                wmma::mma_sync(acc1, al, bh, acc1);
            }
            __syncthreads();   // also guards the W->C union reuse below
        }
        wmma::store_matrix_sync(U.C + n0, acc0, C_LD, wmma::mem_row_major);
        wmma::store_matrix_sync(U.C + n0 + 16, acc1, C_LD, wmma::mem_row_major);
    }
    __syncthreads();

    // ---------- epilogue: bias + ELU + store (+ fp16 mirror on layer 0) ----------
    int tx = tid & 31;   // col group: cols tx*4 .. tx*4+3
    int ty = tid >> 5;   // 0..3: rows ty + 4*r
    float4 bv = *(const float4*)(bias + tx * 4);
    #pragma unroll
    for (int r = 0; r < 4; r++) {
        int rt = ty + r * 4;
        int gr = row0 + rt;
        if (gr < n) {
            float4 o;
            o.x = U.C[rt * C_LD + tx * 4 + 0] + bv.x;
            o.y = U.C[rt * C_LD + tx * 4 + 1] + bv.y;
            o.z = U.C[rt * C_LD + tx * 4 + 2] + bv.z;
            o.w = U.C[rt * C_LD + tx * 4 + 3] + bv.w;
            o.x = o.x > 0.f ? o.x : (__expf(o.x) - 1.0f);
            o.y = o.y > 0.f ? o.y : (__expf(o.y) - 1.0f);
            o.z = o.z > 0.f ? o.z : (__expf(o.z) - 1.0f);
            o.w = o.w > 0.f ? o.w : (__expf(o.w) - 1.0f);
            *(float4*)(out + (long long)gr * D + tx * 4) = o;
            if (write_h1) {
                uint2 p;
                __half2 h01 = __floats2half2_rn(o.x, o.y);
                __half2 h23 = __floats2half2_rn(o.z, o.w);
                p.x = *(unsigned*)&h01;
                p.y = *(unsigned*)&h23;
                *(uint2*)(g_xh + (long long)gr * (D / 2) + tx * 2) = p;
            }
        }
    }
}

// ---------------- launch ----------------
extern "C" void kernel_launch(void* const* d_in, const int* in_sizes, int n_in,
                              void* d_out, int out_size) {
    const float* x   = (const float*)d_in[0];
    const int*   ei  = (const int*)d_in[1];      // int32 edge_index [2, E]
    const float* Wl0 = (const float*)d_in[2];
    const float* b0  = (const float*)d_in[3];
    const float* Wr0 = (const float*)d_in[4];
    const float* Wl1 = (const float*)d_in[5];
    const float* b1  = (const float*)d_in[6];
    const float* Wr1 = (const float*)d_in[7];
    float*       out = (float*)d_out;

    const int N = in_sizes[0] / D;          // 10000
    const int E = in_sizes[1] / 2;          // 640000

    // prep (zero counters + split W + x->fp16) then bucket scatter
    const int prepThreads = N * CNT_STRIDE;        // 320000 (covers W split and x conv)
    prep_kernel<<<(prepThreads + 255) / 256, 256>>>(x, Wl0, Wr0, Wl1, Wr1, N);
    scatter_kernel<<<(E + 255) / 256, 256>>>(ei, E, N);

    const int blocks = (N + TILE - 1) / TILE;      // 625

    // layer 0: fused agg+tensor-gemm -> g_h1 (+ fp16 mirror)
    fused_layer_kernel<<<blocks, NTHREADS>>>(x, false, 0, b0, nullptr, true, N);
    // layer 1: fused agg+tensor-gemm -> d_out
    fused_layer_kernel<<<blocks, NTHREADS>>>(nullptr, true, 1, b1, out, false, N);
}